// round 7
// baseline (speedup 1.0000x reference)
#include <cuda_runtime.h>
#include <cuda_bf16.h>
#include <math.h>
#include <cstdint>

#define Nn 8192
#define Dd 64

// ---------------- device scratch ----------------
__device__ __nv_bfloat16 g_zmp_bf[Nn * Dd];
__device__ __nv_bfloat16 g_zsc_bf[Nn * Dd];
__device__ unsigned g_bits [(size_t)Nn * Nn / 32];  // pos bitmask, 8 MB
__device__ unsigned g_bitsT[(size_t)Nn * Nn / 32];  // transposed bitmask
__device__ float    g_acc[8][Nn];                   // (A,B) for 4 terms

__device__ __forceinline__ unsigned smem_u32(const void* p) {
    unsigned a;
    asm("{ .reg .u64 t; cvta.to.shared.u64 t, %1; cvt.u32.u64 %0, t; }" : "=r"(a) : "l"(p));
    return a;
}
__device__ __forceinline__ float ex2(float x) {   // 2^x, 1 MUFU
    float r; asm("ex2.approx.f32 %0, %1;" : "=f"(r) : "f"(x)); return r;
}
#define EXPC 2.8853900817779268f   // 2*log2(e): exp(2v) = 2^(v*EXPC)

#define LDSM_X4(r0, r1, r2, r3, addr) \
    asm volatile("ldmatrix.sync.aligned.m8n8.x4.shared.b16 {%0,%1,%2,%3}, [%4];" \
                 : "=r"(r0), "=r"(r1), "=r"(r2), "=r"(r3) : "r"(addr))

#define MMA_BF16(c, a0, a1, a2, a3, b0, b1) \
    asm volatile("mma.sync.aligned.m16n8k16.row.col.f32.bf16.bf16.f32 " \
                 "{%0,%1,%2,%3}, {%4,%5,%6,%7}, {%8,%9}, {%0,%1,%2,%3};" \
                 : "+f"((c)[0]), "+f"((c)[1]), "+f"((c)[2]), "+f"((c)[3]) \
                 : "r"(a0), "r"(a1), "r"(a2), "r"(a3), "r"(b0), "r"(b1))

#define CP16(dst, src) \
    asm volatile("cp.async.cg.shared.global [%0], [%1], 16;" :: "r"(dst), "l"(src))
#define CP_COMMIT() asm volatile("cp.async.commit_group;" ::: "memory")
#define CP_WAIT0()  asm volatile("cp.async.wait_group 0;" ::: "memory")

// ---------------- kernel 1: zero accumulators ----------------
__global__ void zero_acc_kernel() {
    int i = blockIdx.x * blockDim.x + threadIdx.x;
    if (i < 8 * Nn) ((float*)g_acc)[i] = 0.0f;
}

// ---------------- kernel 2: row L2-normalize -> bf16 ----------------
__global__ void normalize_kernel(const float* __restrict__ z, int which) {
    __nv_bfloat16* out = which ? g_zsc_bf : g_zmp_bf;
    int row  = blockIdx.x * 8 + (threadIdx.x >> 5);
    int lane = threadIdx.x & 31;
    float2 v = ((const float2*)(z + (size_t)row * Dd))[lane];
    float s = v.x * v.x + v.y * v.y;
    #pragma unroll
    for (int o = 16; o; o >>= 1) s += __shfl_xor_sync(0xffffffffu, s, o);
    float inv = 1.0f / fmaxf(sqrtf(s), 1e-12f);
    __nv_bfloat162 h = __floats2bfloat162_rn(v.x * inv, v.y * inv);
    ((__nv_bfloat162*)(out + (size_t)row * Dd))[lane] = h;
}

// ---------------- kernel 3: pack pos into bitmask (4-way MLP) ----------------
#define PK_Q (Nn * (size_t)Nn / 16)        // float4s per quarter
__global__ void pack_pos_kernel(const float4* __restrict__ pos4) {
    unsigned base = blockIdx.x * blockDim.x + threadIdx.x;
    unsigned lane = threadIdx.x & 31;
    #pragma unroll
    for (int h = 0; h < 4; h++) {
        unsigned idx4 = base + (unsigned)(h * PK_Q);
        float4 v = pos4[idx4];
        unsigned nib = (v.x != 0.f ? 1u : 0u) | (v.y != 0.f ? 2u : 0u) |
                       (v.z != 0.f ? 4u : 0u) | (v.w != 0.f ? 8u : 0u);
        unsigned word = nib << (4 * (lane & 7));
        word |= __shfl_xor_sync(0xffffffffu, word, 1);
        word |= __shfl_xor_sync(0xffffffffu, word, 2);
        word |= __shfl_xor_sync(0xffffffffu, word, 4);
        if ((lane & 7) == 0) g_bits[idx4 >> 3] = word;
    }
}

// ---------------- kernel 3b: 32x32 ballot bit-transpose ----------------
__global__ void transpose_bits_kernel() {
    unsigned wb = blockIdx.x * 8 + (threadIdx.x >> 5);
    unsigned lane = threadIdx.x & 31;
    unsigned R = wb & 255, C = wb >> 8;
    unsigned w = g_bits[(size_t)(R * 32 + lane) * 256 + C];
    unsigned out = 0;
    #pragma unroll
    for (int l = 0; l < 32; l++) {
        unsigned bal = __ballot_sync(0xffffffffu, (w >> l) & 1u);
        if (lane == (unsigned)l) out = bal;
    }
    g_bitsT[(size_t)(C * 32 + lane) * 256 + R] = out;
}

// ---------------- kernel 4: HMMA similarity, flattened 8256-CTA grid ----------------
// t < 4096: mode 0 (mp,sc) full grid (row term 0 + col term 1 = M1^T).
// next 2080: mode 1 (mp,mp) upper triangle; next 2080: mode 2 (sc,sc).
#define NT0  4096
#define NTRI 2080
#define A_OFF     0
#define B_OFF     16384
#define BITS_OFF  32768
#define BITST_OFF 34816
#define COL_OFF   36864      // colacc[8 warps][2][128] floats = 8 KB
#define SMEM_SZ   45056

__global__ __launch_bounds__(256, 2) void sim_mma_kernel() {
    int t = blockIdx.x, mode, bi, bj;
    if (t < NT0) {
        mode = 0; bi = t >> 6; bj = t & 63;
    } else {
        t -= NT0;
        mode = 1 + (t >= NTRI);
        if (t >= NTRI) t -= NTRI;
        float f = 64.5f - sqrtf(64.5f * 64.5f - 2.0f * (float)t);
        bi = (int)f;
        while ((bi + 1) * 64 - ((bi + 1) * bi) / 2 <= t) bi++;
        while (bi * 64 - (bi * (bi - 1)) / 2 > t) bi--;
        bj = bi + (t - (bi * 64 - (bi * (bi - 1)) / 2));
    }
    const bool colSide = (mode == 0) || (bi < bj);

    __shared__ __align__(128) unsigned char sm[SMEM_SZ];
    const unsigned smb = smem_u32(sm);

    const __nv_bfloat16* Ap = (mode == 2) ? g_zsc_bf : g_zmp_bf;
    const __nv_bfloat16* Bp = (mode == 1) ? g_zmp_bf : g_zsc_bf;
    const int tid = threadIdx.x, lane = tid & 31, w = tid >> 5;

    // ---- stage tiles (swizzled) via cp.async ----
    const char* Ag = (const char*)(Ap + (size_t)bi * 128 * Dd);
    const char* Bg = (const char*)(Bp + (size_t)bj * 128 * Dd);
    #pragma unroll
    for (int i = 0; i < 4; i++) {
        int seg = i * 256 + tid;
        int row = seg >> 3, c = seg & 7;
        unsigned off = row * 128 + ((c ^ (row & 7)) << 4);
        CP16(smb + A_OFF + off, Ag + row * 128 + c * 16);
        CP16(smb + B_OFF + off, Bg + row * 128 + c * 16);
    }
    if (tid < 128) {
        const size_t bidx = (size_t)(bi * 128 + tid) * 256 + bj * 4;
        CP16(smb + BITS_OFF + tid * 16, (const char*)(g_bits + bidx));
        CP16(smb + BITST_OFF + tid * 16, (const char*)(g_bitsT + bidx));
    }
    #pragma unroll
    for (int i = 0; i < 8; i++)
        ((float*)(sm + COL_OFF))[i * 256 + tid] = 0.f;
    CP_COMMIT();
    CP_WAIT0();
    __syncthreads();

    // ---- A fragments for all 4 k-steps ----
    const int rA = w * 16 + (lane & 15);
    const int cA_sel = lane >> 4;
    const unsigned aBase = smb + A_OFF + rA * 128;
    unsigned a[4][4];
    #pragma unroll
    for (int ks = 0; ks < 4; ks++) {
        unsigned ca = 2 * ks + cA_sel;
        LDSM_X4(a[ks][0], a[ks][1], a[ks][2], a[ks][3], aBase + ((ca ^ (rA & 7)) << 4));
    }

    const int nB = (lane & 7) + ((lane >> 4) & 1) * 8;
    const int cB_sel = (lane >> 3) & 1;
    const int qr = lane >> 2, qc = lane & 3;
    const int r_lo = w * 16 + qr, r_hi = r_lo + 8;

    float s_lo = 0.f, p_lo = 0.f, s_hi = 0.f, p_hi = 0.f;
    float* colacc = (float*)(sm + COL_OFF);

    #pragma unroll
    for (int nb = 0; nb < 4; nb++) {
        float acc[4][4];
        #pragma unroll
        for (int u = 0; u < 4; u++)
            #pragma unroll
            for (int j = 0; j < 4; j++) acc[u][j] = 0.f;

        #pragma unroll
        for (int ks = 0; ks < 4; ks++) {
            unsigned cb = 2 * ks + cB_sel;
            #pragma unroll
            for (int g = 0; g < 2; g++) {
                int col = nb * 32 + g * 16 + nB;
                unsigned b0, b1, b2, b3;
                LDSM_X4(b0, b1, b2, b3, smb + B_OFF + col * 128 + ((cb ^ (col & 7)) << 4));
                MMA_BF16(acc[2 * g + 0], a[ks][0], a[ks][1], a[ks][2], a[ks][3], b0, b1);
                MMA_BF16(acc[2 * g + 1], a[ks][0], a[ks][1], a[ks][2], a[ks][3], b2, b3);
            }
        }

        // bits for this 32-col block, loaded from smem (not held across mainloop)
        unsigned bl, bh, tl, th;
        asm volatile("ld.shared.b32 %0, [%1];" : "=r"(bl) : "r"(smb + BITS_OFF  + r_lo * 16 + nb * 4));
        asm volatile("ld.shared.b32 %0, [%1];" : "=r"(bh) : "r"(smb + BITS_OFF  + r_hi * 16 + nb * 4));
        asm volatile("ld.shared.b32 %0, [%1];" : "=r"(tl) : "r"(smb + BITST_OFF + r_lo * 16 + nb * 4));
        asm volatile("ld.shared.b32 %0, [%1];" : "=r"(th) : "r"(smb + BITST_OFF + r_hi * 16 + nb * 4));

        #pragma unroll
        for (int u = 0; u < 4; u++) {
            const int sb = u * 8 + qc * 2;
            float e0 = ex2(acc[u][0] * EXPC);
            float e1 = ex2(acc[u][1] * EXPC);
            float e2 = ex2(acc[u][2] * EXPC);
            float e3 = ex2(acc[u][3] * EXPC);
            unsigned l = bl >> sb, h = bh >> sb;
            s_lo += e0 + e1;
            s_hi += e2 + e3;
            p_lo += ((l & 1u) ? e0 : 0.f) + ((l & 2u) ? e1 : 0.f);
            p_hi += ((h & 1u) ? e2 : 0.f) + ((h & 2u) ? e3 : 0.f);

            if (colSide) {
                unsigned cl = tl >> sb, ch = th >> sb;
                float c0s = e0 + e2, c1s = e1 + e3;
                float c0p = ((cl & 1u) ? e0 : 0.f) + ((ch & 1u) ? e2 : 0.f);
                float c1p = ((cl & 2u) ? e1 : 0.f) + ((ch & 2u) ? e3 : 0.f);
                #pragma unroll
                for (int o = 4; o <= 16; o <<= 1) {
                    c0s += __shfl_xor_sync(0xffffffffu, c0s, o);
                    c1s += __shfl_xor_sync(0xffffffffu, c1s, o);
                    c0p += __shfl_xor_sync(0xffffffffu, c0p, o);
                    c1p += __shfl_xor_sync(0xffffffffu, c1p, o);
                }
                if (qr == 0) {
                    int col = nb * 32 + u * 8 + qc * 2;
                    colacc[(w * 2 + 0) * 128 + col]     = c0s;
                    colacc[(w * 2 + 0) * 128 + col + 1] = c1s;
                    colacc[(w * 2 + 1) * 128 + col]     = c0p;
                    colacc[(w * 2 + 1) * 128 + col + 1] = c1p;
                }
            }
        }
    }

    // ---- row-side reduce + atomics ----
    const int rowBase = (mode == 0) ? 0 : ((mode == 1) ? 4 : 6);
    #pragma unroll
    for (int o = 1; o <= 2; o <<= 1) {
        s_lo += __shfl_xor_sync(0xffffffffu, s_lo, o);
        p_lo += __shfl_xor_sync(0xffffffffu, p_lo, o);
        s_hi += __shfl_xor_sync(0xffffffffu, s_hi, o);
        p_hi += __shfl_xor_sync(0xffffffffu, p_hi, o);
    }
    if (qc == 0) {
        atomicAdd(&g_acc[rowBase + 0][bi * 128 + r_lo], s_lo);
        atomicAdd(&g_acc[rowBase + 1][bi * 128 + r_lo], p_lo);
        atomicAdd(&g_acc[rowBase + 0][bi * 128 + r_hi], s_hi);
        atomicAdd(&g_acc[rowBase + 1][bi * 128 + r_hi], p_hi);
    }

    // ---- col-side flush ----
    if (colSide) {
        const int colBase = (mode == 0) ? 2 : rowBase;
        __syncthreads();
        if (tid < 128) {
            float cs = 0.f, cp = 0.f;
            #pragma unroll
            for (int w2 = 0; w2 < 8; w2++) {
                cs += colacc[(w2 * 2 + 0) * 128 + tid];
                cp += colacc[(w2 * 2 + 1) * 128 + tid];
            }
            atomicAdd(&g_acc[colBase + 0][bj * 128 + tid], cs);
            atomicAdd(&g_acc[colBase + 1][bj * 128 + tid], cp);
        }
    }
}

// ---------------- kernel 5: finalize loss ----------------
__global__ void finalize_kernel(float* out) {
    __shared__ double sred[256];
    double local = 0.0;
    for (int i = threadIdx.x; i < Nn; i += 256) {
        #pragma unroll
        for (int t = 0; t < 4; t++) {
            double A = (double)g_acc[2 * t][i];
            double B = (double)g_acc[2 * t + 1][i];
            local += log(B) - log(A + 1e-8);
        }
    }
    sred[threadIdx.x] = local;
    __syncthreads();
    for (int o = 128; o; o >>= 1) {
        if (threadIdx.x < o) sred[threadIdx.x] += sred[threadIdx.x + o];
        __syncthreads();
    }
    if (threadIdx.x == 0) out[0] = (float)(-sred[0] / (double)Nn);
}

// ---------------- launch ----------------
extern "C" void kernel_launch(void* const* d_in, const int* in_sizes, int n_in,
                              void* d_out, int out_size) {
    const float* z_mp = (const float*)d_in[0];
    const float* z_sc = (const float*)d_in[1];
    const float* pos  = (const float*)d_in[2];
    float* out = (float*)d_out;

    zero_acc_kernel<<<256, 256>>>();
    normalize_kernel<<<Nn / 8, 256>>>(z_mp, 0);
    normalize_kernel<<<Nn / 8, 256>>>(z_sc, 1);
    pack_pos_kernel<<<16384, 256>>>((const float4*)pos);
    transpose_bits_kernel<<<8192, 256>>>();
    sim_mma_kernel<<<NT0 + 2 * NTRI, 256>>>();
    finalize_kernel<<<1, 256>>>(out);
}

// round 8
// speedup vs baseline: 1.4658x; 1.4658x over previous
#include <cuda_runtime.h>
#include <cuda_bf16.h>
#include <math.h>
#include <cstdint>

#define Nn 8192
#define Dd 64

// ---------------- device scratch ----------------
__device__ __nv_bfloat16 g_zmp_bf[Nn * Dd];
__device__ __nv_bfloat16 g_zsc_bf[Nn * Dd];
__device__ unsigned g_bits[(size_t)Nn * Nn / 32];   // pos bitmask, 8 MB
__device__ float    g_acc[8][Nn];                   // (A,B) for 4 terms
__device__ double   g_loss;

__device__ __forceinline__ unsigned smem_u32(const void* p) {
    unsigned a;
    asm("{ .reg .u64 t; cvta.to.shared.u64 t, %1; cvt.u32.u64 %0, t; }" : "=r"(a) : "l"(p));
    return a;
}
__device__ __forceinline__ float ex2(float x) {   // 2^x, 1 MUFU
    float r; asm("ex2.approx.f32 %0, %1;" : "=f"(r) : "f"(x)); return r;
}
#define EXPC 2.8853900817779268f   // 2*log2(e): exp(2v) = 2^(v*EXPC)

#define LDSM_X4(r0, r1, r2, r3, addr) \
    asm volatile("ldmatrix.sync.aligned.m8n8.x4.shared.b16 {%0,%1,%2,%3}, [%4];" \
                 : "=r"(r0), "=r"(r1), "=r"(r2), "=r"(r3) : "r"(addr))

#define MMA_BF16(c, a0, a1, a2, a3, b0, b1) \
    asm volatile("mma.sync.aligned.m16n8k16.row.col.f32.bf16.bf16.f32 " \
                 "{%0,%1,%2,%3}, {%4,%5,%6,%7}, {%8,%9}, {%0,%1,%2,%3};" \
                 : "+f"((c)[0]), "+f"((c)[1]), "+f"((c)[2]), "+f"((c)[3]) \
                 : "r"(a0), "r"(a1), "r"(a2), "r"(a3), "r"(b0), "r"(b1))

#define CP16(dst, src) \
    asm volatile("cp.async.cg.shared.global [%0], [%1], 16;" :: "r"(dst), "l"(src))
#define CP_COMMIT() asm volatile("cp.async.commit_group;" ::: "memory")
#define CP_WAIT0()  asm volatile("cp.async.wait_group 0;" ::: "memory")

// ---------------- kernel 1: zero accumulators + loss ----------------
__global__ void zero_acc_kernel() {
    int i = blockIdx.x * blockDim.x + threadIdx.x;
    if (i < 8 * Nn) ((float*)g_acc)[i] = 0.0f;
    if (i == 0) g_loss = 0.0;
}

// ---------------- kernel 2: row L2-normalize -> bf16 ----------------
__global__ void normalize_kernel(const float* __restrict__ z, int which) {
    __nv_bfloat16* out = which ? g_zsc_bf : g_zmp_bf;
    int row  = blockIdx.x * 8 + (threadIdx.x >> 5);
    int lane = threadIdx.x & 31;
    float2 v = ((const float2*)(z + (size_t)row * Dd))[lane];
    float s = v.x * v.x + v.y * v.y;
    #pragma unroll
    for (int o = 16; o; o >>= 1) s += __shfl_xor_sync(0xffffffffu, s, o);
    float inv = 1.0f / fmaxf(sqrtf(s), 1e-12f);
    __nv_bfloat162 h = __floats2bfloat162_rn(v.x * inv, v.y * inv);
    ((__nv_bfloat162*)(out + (size_t)row * Dd))[lane] = h;
}

// ---------------- kernel 3: pack pos into bitmask (8-way MLP) ----------------
#define PK_8 (Nn * (size_t)Nn / 32)        // float4s per eighth
__global__ void pack_pos_kernel(const float4* __restrict__ pos4) {
    unsigned base = blockIdx.x * blockDim.x + threadIdx.x;
    unsigned lane = threadIdx.x & 31;
    #pragma unroll
    for (int h = 0; h < 8; h++) {
        unsigned idx4 = base + (unsigned)(h * PK_8);
        float4 v = pos4[idx4];
        unsigned nib = (v.x != 0.f ? 1u : 0u) | (v.y != 0.f ? 2u : 0u) |
                       (v.z != 0.f ? 4u : 0u) | (v.w != 0.f ? 8u : 0u);
        unsigned word = nib << (4 * (lane & 7));
        word |= __shfl_xor_sync(0xffffffffu, word, 1);
        word |= __shfl_xor_sync(0xffffffffu, word, 2);
        word |= __shfl_xor_sync(0xffffffffu, word, 4);
        if ((lane & 7) == 0) g_bits[idx4 >> 3] = word;
    }
}

// ---------------- kernel 4: HMMA similarity, streaming 32-col blocks ----------------
// grid (64, 64, 4); mode: 0=(mp,sc) 1=(sc,mp) 2=(mp,mp) 3=(sc,sc). 128x128 tile/CTA.
#define A_OFF    0
#define B_OFF    16384
#define BITS_OFF 32768      // 128 rows x uint4
#define SMEM_SZ  34816

__global__ __launch_bounds__(256, 3) void sim_mma_kernel() {
    __shared__ __align__(128) unsigned char sm[SMEM_SZ];
    const unsigned smb = smem_u32(sm);

    const int mode = blockIdx.z;
    const __nv_bfloat16* Ap = (mode == 1 || mode == 3) ? g_zsc_bf : g_zmp_bf;
    const __nv_bfloat16* Bp = (mode == 0 || mode == 3) ? g_zsc_bf : g_zmp_bf;
    const int bi = blockIdx.y, bj = blockIdx.x;
    const int tid = threadIdx.x, lane = tid & 31, w = tid >> 5;

    // ---- stage tiles (swizzled) via cp.async ----
    const char* Ag = (const char*)(Ap + (size_t)bi * 128 * Dd);
    const char* Bg = (const char*)(Bp + (size_t)bj * 128 * Dd);
    #pragma unroll
    for (int i = 0; i < 4; i++) {
        int seg = i * 256 + tid;                 // 1024 segs of 16 B per tile
        int row = seg >> 3, c = seg & 7;
        unsigned off = row * 128 + ((c ^ (row & 7)) << 4);
        CP16(smb + A_OFF + off, Ag + row * 128 + c * 16);
        CP16(smb + B_OFF + off, Bg + row * 128 + c * 16);
    }
    if (tid < 128)
        CP16(smb + BITS_OFF + tid * 16,
             (const char*)(g_bits + (size_t)(bi * 128 + tid) * 256 + bj * 4));
    CP_COMMIT();
    CP_WAIT0();
    __syncthreads();

    // ---- A fragments for all 4 k-steps (held in regs) ----
    const int rA = w * 16 + (lane & 15);
    const int cA_sel = lane >> 4;
    const unsigned aBase = smb + A_OFF + rA * 128;
    unsigned a[4][4];
    #pragma unroll
    for (int ks = 0; ks < 4; ks++) {
        unsigned ca = 2 * ks + cA_sel;
        LDSM_X4(a[ks][0], a[ks][1], a[ks][2], a[ks][3], aBase + ((ca ^ (rA & 7)) << 4));
    }

    const int nB = (lane & 7) + ((lane >> 4) & 1) * 8;
    const int cB_sel = (lane >> 3) & 1;
    const int qr = lane >> 2, qc = lane & 3;
    const int r_lo = w * 16 + qr, r_hi = r_lo + 8;

    uint4 wl4 = *(const uint4*)(sm + BITS_OFF + r_lo * 16);
    uint4 wh4 = *(const uint4*)(sm + BITS_OFF + r_hi * 16);
    unsigned wlo[4] = { wl4.x, wl4.y, wl4.z, wl4.w };
    unsigned whi[4] = { wh4.x, wh4.y, wh4.z, wh4.w };

    float s_lo = 0.f, p_lo = 0.f, s_hi = 0.f, p_hi = 0.f;

    #pragma unroll
    for (int nb = 0; nb < 4; nb++) {
        float acc[4][4];
        #pragma unroll
        for (int u = 0; u < 4; u++)
            #pragma unroll
            for (int j = 0; j < 4; j++) acc[u][j] = 0.f;

        #pragma unroll
        for (int ks = 0; ks < 4; ks++) {
            unsigned cb = 2 * ks + cB_sel;
            #pragma unroll
            for (int g = 0; g < 2; g++) {
                int col = nb * 32 + g * 16 + nB;
                unsigned b0, b1, b2, b3;
                LDSM_X4(b0, b1, b2, b3, smb + B_OFF + col * 128 + ((cb ^ (col & 7)) << 4));
                MMA_BF16(acc[2 * g + 0], a[ks][0], a[ks][1], a[ks][2], a[ks][3], b0, b1);
                MMA_BF16(acc[2 * g + 1], a[ks][0], a[ks][1], a[ks][2], a[ks][3], b2, b3);
            }
        }

        const unsigned bl = wlo[nb], bh = whi[nb];
        #pragma unroll
        for (int u = 0; u < 4; u++) {
            const int sb = u * 8 + qc * 2;
            float e0 = ex2(acc[u][0] * EXPC);
            float e1 = ex2(acc[u][1] * EXPC);
            float e2 = ex2(acc[u][2] * EXPC);
            float e3 = ex2(acc[u][3] * EXPC);
            unsigned l = bl >> sb, h = bh >> sb;
            s_lo += e0 + e1;
            s_hi += e2 + e3;
            p_lo += ((l & 1u) ? e0 : 0.f) + ((l & 2u) ? e1 : 0.f);
            p_hi += ((h & 1u) ? e2 : 0.f) + ((h & 2u) ? e3 : 0.f);
        }
    }

    #pragma unroll
    for (int o = 1; o <= 2; o <<= 1) {
        s_lo += __shfl_xor_sync(0xffffffffu, s_lo, o);
        p_lo += __shfl_xor_sync(0xffffffffu, p_lo, o);
        s_hi += __shfl_xor_sync(0xffffffffu, s_hi, o);
        p_hi += __shfl_xor_sync(0xffffffffu, p_hi, o);
    }
    if (qc == 0) {
        atomicAdd(&g_acc[2 * mode + 0][bi * 128 + r_lo], s_lo);
        atomicAdd(&g_acc[2 * mode + 1][bi * 128 + r_lo], p_lo);
        atomicAdd(&g_acc[2 * mode + 0][bi * 128 + r_hi], s_hi);
        atomicAdd(&g_acc[2 * mode + 1][bi * 128 + r_hi], p_hi);
    }
}

// ---------------- kernel 5a: parallel partial finalize ----------------
__global__ void finalize_part_kernel() {
    __shared__ double sred[128];
    int i = blockIdx.x * 128 + threadIdx.x;     // one row per thread, 64 blocks
    double local = 0.0;
    #pragma unroll
    for (int t = 0; t < 4; t++) {
        double A = (double)g_acc[2 * t][i];
        double B = (double)g_acc[2 * t + 1][i];
        local += log(B) - log(A + 1e-8);
    }
    sred[threadIdx.x] = local;
    __syncthreads();
    for (int o = 64; o; o >>= 1) {
        if (threadIdx.x < o) sred[threadIdx.x] += sred[threadIdx.x + o];
        __syncthreads();
    }
    if (threadIdx.x == 0) atomicAdd(&g_loss, sred[0]);
}

// ---------------- kernel 5b: emit scalar ----------------
__global__ void finalize_out_kernel(float* out) {
    out[0] = (float)(-g_loss / (double)Nn);
}

// ---------------- launch ----------------
extern "C" void kernel_launch(void* const* d_in, const int* in_sizes, int n_in,
                              void* d_out, int out_size) {
    const float* z_mp = (const float*)d_in[0];
    const float* z_sc = (const float*)d_in[1];
    const float* pos  = (const float*)d_in[2];
    float* out = (float*)d_out;

    zero_acc_kernel<<<256, 256>>>();
    normalize_kernel<<<Nn / 8, 256>>>(z_mp, 0);
    normalize_kernel<<<Nn / 8, 256>>>(z_sc, 1);
    pack_pos_kernel<<<8192, 256>>>((const float4*)pos);   // 8 float4s per thread
    dim3 g(Nn / 128, Nn / 128, 4);
    sim_mma_kernel<<<g, 256>>>();
    finalize_part_kernel<<<64, 128>>>();
    finalize_out_kernel<<<1, 1>>>(out);
}